// round 16
// baseline (speedup 1.0000x reference)
#include <cuda_runtime.h>
#include <math.h>

// Problem constants
#define BATCH   4
#define NNODES  325
#define BN      (BATCH * NNODES)   // 1300
#define IDIM    64
#define HDIM    128
#define G4H     (4 * HDIM)         // 512
#define MAXNB   96
#define LN_EPS  1e-5f
#define TM      16                  // rows per GEMM tile
#define NT      82                  // 82*16 = 1312 >= 1300

// ---------------- scratch (__device__ globals; no allocation) ----------------
__device__ float g_gates[BN * G4H];
__device__ float g_h_lstm[BN * HDIM];
__device__ float g_support[BN * HDIM];
__device__ float g_P[BN * HDIM];
__device__ float g_Q[BN * HDIM];
__device__ float g_hgraph[BN * HDIM];
__device__ float g_s[BN * HDIM];
__device__ float g_t[BN * HDIM];
__device__ float g_hatt[BN * HDIM];
__device__ int   g_nbr[BN * MAXNB];
__device__ float g_nbrw[BN * MAXNB];
__device__ int   g_cnt[BN];
__device__ float g_sconst[HDIM];            // gc_b @ Ws^T + Ws_b
__device__ float g_tconst[HDIM];            // gc_b @ Wt^T + Wt_b
// packed weights (coalesced [k][col] layouts)
__device__ float g_Wlstm[192 * G4H];        // rows 0-63: W_ih^T, 64-191: W_hh^T
__device__ float g_Wspq[HDIM * 384];        // cols 0-127 gc_w, 128-255 gc_w@Ws^T, 256-383 gc_w@Wt^T
__device__ float g_comb_t[2 * HDIM * HDIM]; // [256][128]

__device__ __forceinline__ float sigm_fast(float x) {
    return __fdividef(1.0f, 1.0f + __expf(-x));
}
__device__ __forceinline__ float tanh_fast(float x) {
    float cx = fminf(fmaxf(x, -15.0f), 15.0f);
    float e = __expf(2.0f * cx);
    return __fdividef(e - 1.0f, e + 1.0f);
}

// ============================================================================
// K0: prep = weight stacking/transposes + adjacency scan + s/t bias constants.
// ============================================================================
#define TW_TOTAL (192 * G4H + 2 * HDIM * HDIM)
#define NTB ((TW_TOTAL + 255) / 256)   // 512
#define SCANB ((BN + 7) / 8)           // 163
__global__ void __launch_bounds__(256)
prep_kernel(const float* __restrict__ W_ih, const float* __restrict__ W_hh,
            const float* __restrict__ comb_w, const float* __restrict__ adj,
            const float* __restrict__ gc_b, const float* __restrict__ Ws_w,
            const float* __restrict__ Ws_b, const float* __restrict__ Wt_w,
            const float* __restrict__ Wt_b)
{
    if (blockIdx.x < NTB) {
        int idx = blockIdx.x * 256 + threadIdx.x;
        if (idx < 192 * G4H) {                        // Wlstm [192][512]
            int k = idx >> 9, g = idx & 511;
            g_Wlstm[idx] = (k < 64) ? __ldg(W_ih + g * IDIM + k)
                                    : __ldg(W_hh + g * HDIM + (k - 64));
            return;
        }
        idx -= 192 * G4H;
        if (idx < 2 * HDIM * HDIM) {                  // comb_t [256][128]
            int k = idx >> 7, o = idx & 127;
            g_comb_t[idx] = __ldg(comb_w + o * 2 * HDIM + k);
        }
        return;
    }

    if (blockIdx.x < NTB + SCANB) {
        // ---- adjacency scan: 8 warps, one row per warp, ballot compaction ----
        const int lane = threadIdx.x & 31;
        const int wrp  = threadIdx.x >> 5;
        const int row  = (blockIdx.x - NTB) * 8 + wrp;
        if (row >= BN) return;
        const int b = row / NNODES;
        const int i = row % NNODES;
        const float* arow = adj + (size_t)b * NNODES * NNODES + (size_t)i * NNODES;

        int cnt = 0;
        const unsigned lt = (1u << lane) - 1u;
        for (int j0 = 0; j0 < NNODES; j0 += 32) {
            int j = j0 + lane;
            float a = (j < NNODES) ? __ldg(arow + j) : 0.0f;
            unsigned m = __ballot_sync(0xffffffffu, a != 0.0f);
            int pos = cnt + __popc(m & lt);
            if (a != 0.0f && pos < MAXNB) {
                g_nbr[row * MAXNB + pos]  = j;
                g_nbrw[row * MAXNB + pos] = a;
            }
            cnt += __popc(m);
        }
        if (lane == 0) g_cnt[row] = min(cnt, MAXNB);
        return;
    }

    // ---- bias constants: sconst = gc_b @ Ws^T + Ws_b; tconst likewise ----
    __shared__ float gb[HDIM];
    int tid = threadIdx.x;
    if (tid < HDIM) gb[tid] = __ldg(gc_b + tid);
    __syncthreads();
    int o = tid & 127;
    const float* W = (tid < HDIM) ? (Ws_w + o * HDIM) : (Wt_w + o * HDIM);
    float acc = (tid < HDIM) ? __ldg(Ws_b + o) : __ldg(Wt_b + o);
#pragma unroll 8
    for (int k = 0; k < HDIM; k++)
        acc += gb[k] * __ldg(W + k);
    if (tid < HDIM) g_sconst[o] = acc;
    else            g_tconst[o] = acc;
}

// ============================================================================
// K0b: prep2 = build g_Wspq row k: [gc_w[k][:] | (gc_w@Ws^T)[k][:] | (gc_w@Wt^T)[k][:]]
// Grid 128 (block = k), 256 threads.
// ============================================================================
__global__ void __launch_bounds__(256)
prep2_kernel(const float* __restrict__ gc_w, const float* __restrict__ Ws_w,
             const float* __restrict__ Wt_w)
{
    const int k = blockIdx.x;
    const int tid = threadIdx.x;
    __shared__ float gcrow[HDIM];
    if (tid < HDIM) gcrow[tid] = __ldg(gc_w + k * HDIM + tid);
    __syncthreads();
    if (tid < HDIM) g_Wspq[k * 384 + tid] = gcrow[tid];

    const int o = tid & 127;
    const float* Wrow = (tid < HDIM) ? (Ws_w + o * HDIM) : (Wt_w + o * HDIM);
    float acc = 0.0f;
#pragma unroll 8
    for (int j = 0; j < HDIM; j++)
        acc += gcrow[j] * __ldg(Wrow + j);
    // tid<128 -> col 128+o (Wps); tid>=128 -> col 256+o (Wqt)
    g_Wspq[k * 384 + 128 + (tid & 128) + o] = acc;
}

// ============================================================================
// K1: LSTM gates GEMM, smem-cached chunked.
// Grid (82, 8).  Block: 16 rows x 64 cols.  K=192 in 3 chunks of 64.
// ============================================================================
__global__ void __launch_bounds__(128)
lstm_gemm_kernel(const float* __restrict__ x, const float* __restrict__ h,
                 const float* __restrict__ b_ih, const float* __restrict__ b_hh)
{
    __shared__ __align__(16) float sW[64][64];     // 16KB weight chunk
    __shared__ float sA[TM][196];                  // [x|h] acts, padded

    const int row0 = blockIdx.x * TM;
    const int cg = blockIdx.y;                     // 0..7 (64 cols each)
    const int tid = threadIdx.x;
    const int colq = tid & 15;
    const int rowg = tid >> 4;
    const int oc = colq * 4;
    const int m0 = rowg * 2;

    for (int m = 0; m < TM; m++) {
        int row = row0 + m;
        bool ok = row < BN;
        for (int k = tid; k < 192; k += 128)
            sA[m][k] = ok ? (k < 64 ? x[row * IDIM + k] : h[row * HDIM + k - 64]) : 0.0f;
    }

    float acc[8] = {0.f, 0.f, 0.f, 0.f, 0.f, 0.f, 0.f, 0.f};
    for (int kc = 0; kc < 192; kc += 64) {
        __syncthreads();   // acts ready (1st iter) / prev chunk FFMA done
        for (int idx = tid; idx < 64 * 16; idx += 128) {
            int kk = idx >> 4, c4 = idx & 15;
            *(float4*)&sW[kk][c4 * 4] =
                *(const float4*)&g_Wlstm[(kc + kk) * G4H + cg * 64 + c4 * 4];
        }
        __syncthreads();
#pragma unroll 8
        for (int kk = 0; kk < 64; kk++) {
            float4 w = *(const float4*)&sW[kk][oc];
            float a0 = sA[m0][kc + kk];
            float a1 = sA[m0 + 1][kc + kk];
            acc[0] += a0 * w.x; acc[1] += a0 * w.y; acc[2] += a0 * w.z; acc[3] += a0 * w.w;
            acc[4] += a1 * w.x; acc[5] += a1 * w.y; acc[6] += a1 * w.z; acc[7] += a1 * w.w;
        }
    }

    const int gcol = cg * 64 + oc;
    float4 bi = *(const float4*)&b_ih[gcol];
    float4 bh = *(const float4*)&b_hh[gcol];
    float b0 = bi.x + bh.x, b1 = bi.y + bh.y, b2 = bi.z + bh.z, b3 = bi.w + bh.w;
    int r0 = row0 + m0;
    if (r0 < BN) {
        float4 o0 = {acc[0] + b0, acc[1] + b1, acc[2] + b2, acc[3] + b3};
        *(float4*)&g_gates[r0 * G4H + gcol] = o0;
    }
    if (r0 + 1 < BN) {
        float4 o1 = {acc[4] + b0, acc[5] + b1, acc[6] + b2, acc[7] + b3};
        *(float4*)&g_gates[(r0 + 1) * G4H + gcol] = o1;
    }
}

// ============================================================================
// K2: LSTM activations (pure elementwise).  650 blocks x 256 threads.
// ============================================================================
__global__ void __launch_bounds__(256)
act_kernel(const float* __restrict__ c, float* __restrict__ c_out)
{
    int idx = blockIdx.x * 256 + threadIdx.x;   // exactly BN*HDIM
    int node = idx >> 7, u = idx & 127;
    const float* gb = g_gates + node * G4H;
    float ig = sigm_fast(gb[u]);
    float fg = sigm_fast(gb[HDIM + u]);
    float gg = tanh_fast(gb[2 * HDIM + u]);
    float og = sigm_fast(gb[3 * HDIM + u]);
    float cc = fg * c[idx] + ig * gg;
    g_h_lstm[idx] = og * tanh_fast(cc);
    c_out[idx] = cc;
}

// ============================================================================
// K3: fused support|P|Q GEMM: h_lstm[1300x128] @ Wspq[128x384].
// Grid (82, 6).  K=128 in 2 chunks.
// ============================================================================
__global__ void __launch_bounds__(128)
spq_gemm_kernel()
{
    __shared__ __align__(16) float sW[64][64];
    __shared__ float sA[TM][132];

    const int row0 = blockIdx.x * TM;
    const int cg = blockIdx.y;                     // 0..5
    const int tid = threadIdx.x;
    const int colq = tid & 15;
    const int rowg = tid >> 4;
    const int oc = colq * 4;
    const int m0 = rowg * 2;

    for (int m = 0; m < TM; m++) {
        int row = row0 + m;
        bool ok = row < BN;
        sA[m][tid] = ok ? g_h_lstm[row * HDIM + tid] : 0.0f;
    }

    float acc[8] = {0.f, 0.f, 0.f, 0.f, 0.f, 0.f, 0.f, 0.f};
    for (int kc = 0; kc < 128; kc += 64) {
        __syncthreads();
        for (int idx = tid; idx < 64 * 16; idx += 128) {
            int kk = idx >> 4, c4 = idx & 15;
            *(float4*)&sW[kk][c4 * 4] =
                *(const float4*)&g_Wspq[(kc + kk) * 384 + cg * 64 + c4 * 4];
        }
        __syncthreads();
#pragma unroll 8
        for (int kk = 0; kk < 64; kk++) {
            float4 w = *(const float4*)&sW[kk][oc];
            float a0 = sA[m0][kc + kk];
            float a1 = sA[m0 + 1][kc + kk];
            acc[0] += a0 * w.x; acc[1] += a0 * w.y; acc[2] += a0 * w.z; acc[3] += a0 * w.w;
            acc[4] += a1 * w.x; acc[5] += a1 * w.y; acc[6] += a1 * w.z; acc[7] += a1 * w.w;
        }
    }

    const int gcol = cg * 64 + oc;                 // 0..383
    float* dst = (gcol < 128) ? g_support : (gcol < 256) ? g_P : g_Q;
    const int ocol = gcol & 127;
    int r0 = row0 + m0;
    if (r0 < BN) {
        float4 o0 = {acc[0], acc[1], acc[2], acc[3]};
        *(float4*)&dst[r0 * HDIM + ocol] = o0;
    }
    if (r0 + 1 < BN) {
        float4 o1 = {acc[4], acc[5], acc[6], acc[7]};
        *(float4*)&dst[(r0 + 1) * HDIM + ocol] = o1;
    }
}

// ============================================================================
// K4: triple sparse gather (no weight reads), 4x unrolled.  1300 blocks.
// ============================================================================
__global__ void __launch_bounds__(128)
gather_kernel(const float* __restrict__ gc_b)
{
    const int row = blockIdx.x;
    const int b = row / NNODES;
    const int tid = threadIdx.x;

    __shared__ int   lst[MAXNB];
    __shared__ float wv[MAXNB];

    const int cn = g_cnt[row];
    for (int t = tid; t < cn; t += 128) {
        lst[t] = g_nbr[row * MAXNB + t];
        wv[t]  = g_nbrw[row * MAXNB + t];
    }
    __syncthreads();

    const int u = tid;
    float ah = __ldg(gc_b + u);
    float as = g_sconst[u];
    float at = g_tconst[u];
    const size_t base = (size_t)b * NNODES * HDIM + u;

    int t = 0;
    for (; t + 4 <= cn; t += 4) {
        size_t o0 = base + (size_t)lst[t]     * HDIM;
        size_t o1 = base + (size_t)lst[t + 1] * HDIM;
        size_t o2 = base + (size_t)lst[t + 2] * HDIM;
        size_t o3 = base + (size_t)lst[t + 3] * HDIM;
        float w0 = wv[t], w1 = wv[t + 1], w2 = wv[t + 2], w3 = wv[t + 3];
        float h0 = g_support[o0], h1 = g_support[o1], h2 = g_support[o2], h3 = g_support[o3];
        float p0 = g_P[o0], p1 = g_P[o1], p2 = g_P[o2], p3 = g_P[o3];
        float q0 = g_Q[o0], q1 = g_Q[o1], q2 = g_Q[o2], q3 = g_Q[o3];
        ah += w0 * h0 + w1 * h1 + w2 * h2 + w3 * h3;
        as += w0 * p0 + w1 * p1 + w2 * p2 + w3 * p3;
        at += w0 * q0 + w1 * q1 + w2 * q2 + w3 * q3;
    }
    for (; t < cn; t++) {
        size_t off = base + (size_t)lst[t] * HDIM;
        float w = wv[t];
        ah += w * g_support[off];
        as += w * g_P[off];
        at += w * g_Q[off];
    }
    g_hgraph[row * HDIM + u] = ah;
    g_s[row * HDIM + u] = as;
    g_t[row * HDIM + u] = at;
}

// ============================================================================
// K5: attention + softmax + context + LayerNorm.  1300 blocks, 128 threads.
// ============================================================================
__global__ void __launch_bounds__(128)
attn_kernel(const float* __restrict__ v, const float* __restrict__ ln_g,
            const float* __restrict__ ln_b)
{
    const int row = blockIdx.x;
    const int b = row / NNODES;
    const int tid = threadIdx.x;
    const int lane = tid & 31;
    const int wrp = tid >> 5;

    __shared__ float s_sh[HDIM];
    __shared__ float v_sh[HDIM];
    __shared__ float sc[MAXNB];
    __shared__ int   lst[MAXNB];
    __shared__ float red1[4], red2[4];

    s_sh[tid] = g_s[row * HDIM + tid];
    v_sh[tid] = __ldg(v + tid);
    const int cn = g_cnt[row];
    for (int t = tid; t < cn; t += 128) lst[t] = g_nbr[row * MAXNB + t];
    __syncthreads();

    const float* tb = g_t + (size_t)b * NNODES * HDIM;
    for (int t = wrp; t < cn; t += 4) {
        const float* tj = tb + (size_t)lst[t] * HDIM;
        float x0 = __ldg(tj + lane);
        float x1 = __ldg(tj + lane + 32);
        float x2 = __ldg(tj + lane + 64);
        float x3 = __ldg(tj + lane + 96);
        float p = tanh_fast(s_sh[lane] + x0) * v_sh[lane]
                + tanh_fast(s_sh[lane + 32] + x1) * v_sh[lane + 32]
                + tanh_fast(s_sh[lane + 64] + x2) * v_sh[lane + 64]
                + tanh_fast(s_sh[lane + 96] + x3) * v_sh[lane + 96];
#pragma unroll
        for (int off = 16; off > 0; off >>= 1)
            p += __shfl_xor_sync(0xffffffffu, p, off);
        if (lane == 0) sc[t] = p;
    }
    __syncthreads();

    if (wrp == 0) {
        float mx = -1e30f;
        for (int t = lane; t < cn; t += 32) mx = fmaxf(mx, sc[t]);
#pragma unroll
        for (int off = 16; off > 0; off >>= 1)
            mx = fmaxf(mx, __shfl_xor_sync(0xffffffffu, mx, off));
        float sm = 0.0f;
        for (int t = lane; t < cn; t += 32) {
            float e = __expf(sc[t] - mx);
            sc[t] = e;
            sm += e;
        }
#pragma unroll
        for (int off = 16; off > 0; off >>= 1)
            sm += __shfl_xor_sync(0xffffffffu, sm, off);
        float inv = __fdividef(1.0f, sm);
        for (int t = lane; t < cn; t += 32) sc[t] *= inv;
    }
    __syncthreads();

    const int u = tid;
    float acc = 0.0f;
    const float* hgb = g_hgraph + (size_t)b * NNODES * HDIM;
    int t = 0;
    for (; t + 4 <= cn; t += 4) {
        float h0 = __ldg(hgb + (size_t)lst[t]     * HDIM + u);
        float h1 = __ldg(hgb + (size_t)lst[t + 1] * HDIM + u);
        float h2 = __ldg(hgb + (size_t)lst[t + 2] * HDIM + u);
        float h3 = __ldg(hgb + (size_t)lst[t + 3] * HDIM + u);
        acc += sc[t] * h0 + sc[t + 1] * h1 + sc[t + 2] * h2 + sc[t + 3] * h3;
    }
    for (; t < cn; t++)
        acc += sc[t] * __ldg(hgb + (size_t)lst[t] * HDIM + u);

    float s1 = acc, s2 = acc * acc;
#pragma unroll
    for (int off = 16; off > 0; off >>= 1) {
        s1 += __shfl_xor_sync(0xffffffffu, s1, off);
        s2 += __shfl_xor_sync(0xffffffffu, s2, off);
    }
    if (lane == 0) { red1[wrp] = s1; red2[wrp] = s2; }
    __syncthreads();
    float tot1 = red1[0] + red1[1] + red1[2] + red1[3];
    float tot2 = red2[0] + red2[1] + red2[2] + red2[3];
    float mu = tot1 * (1.0f / HDIM);
    float var = tot2 * (1.0f / HDIM) - mu * mu;
    g_hatt[row * HDIM + u] =
        __ldg(ln_g + u) * (acc - mu) * rsqrtf(var + LN_EPS) + __ldg(ln_b + u);
}

// ============================================================================
// K6: combine GEMM: [hl|ha][1300x256] @ comb_t[256x128] + comb_b.
// Grid (82, 2).  K=256 in 4 chunks.
// ============================================================================
__global__ void __launch_bounds__(128)
comb_gemm_kernel(const float* __restrict__ comb_b, float* __restrict__ out)
{
    __shared__ __align__(16) float sW[64][64];
    __shared__ float sA[TM][260];

    const int row0 = blockIdx.x * TM;
    const int cg = blockIdx.y;                     // 0..1
    const int tid = threadIdx.x;
    const int colq = tid & 15;
    const int rowg = tid >> 4;
    const int oc = colq * 4;
    const int m0 = rowg * 2;

    for (int m = 0; m < TM; m++) {
        int row = row0 + m;
        bool ok = row < BN;
        sA[m][tid]       = ok ? g_h_lstm[row * HDIM + tid] : 0.0f;
        sA[m][tid + 128] = ok ? g_hatt[row * HDIM + tid]  : 0.0f;
    }

    float acc[8] = {0.f, 0.f, 0.f, 0.f, 0.f, 0.f, 0.f, 0.f};
    for (int kc = 0; kc < 256; kc += 64) {
        __syncthreads();
        for (int idx = tid; idx < 64 * 16; idx += 128) {
            int kk = idx >> 4, c4 = idx & 15;
            *(float4*)&sW[kk][c4 * 4] =
                *(const float4*)&g_comb_t[(kc + kk) * HDIM + cg * 64 + c4 * 4];
        }
        __syncthreads();
#pragma unroll 8
        for (int kk = 0; kk < 64; kk++) {
            float4 w = *(const float4*)&sW[kk][oc];
            float a0 = sA[m0][kc + kk];
            float a1 = sA[m0 + 1][kc + kk];
            acc[0] += a0 * w.x; acc[1] += a0 * w.y; acc[2] += a0 * w.z; acc[3] += a0 * w.w;
            acc[4] += a1 * w.x; acc[5] += a1 * w.y; acc[6] += a1 * w.z; acc[7] += a1 * w.w;
        }
    }

    const int gcol = cg * 64 + oc;
    float4 cb = *(const float4*)&comb_b[gcol];
    int r0 = row0 + m0;
    if (r0 < BN) {
        float4 o0 = {acc[0] + cb.x, acc[1] + cb.y, acc[2] + cb.z, acc[3] + cb.w};
        *(float4*)&out[r0 * HDIM + gcol] = o0;
    }
    if (r0 + 1 < BN) {
        float4 o1 = {acc[4] + cb.x, acc[5] + cb.y, acc[6] + cb.z, acc[7] + cb.w};
        *(float4*)&out[(r0 + 1) * HDIM + gcol] = o1;
    }
}

// ============================================================================
extern "C" void kernel_launch(void* const* d_in, const int* in_sizes, int n_in,
                              void* d_out, int out_size)
{
    const float* x      = (const float*)d_in[0];
    const float* adj    = (const float*)d_in[1];
    const float* h      = (const float*)d_in[2];
    const float* c      = (const float*)d_in[3];
    const float* W_ih   = (const float*)d_in[4];
    const float* W_hh   = (const float*)d_in[5];
    const float* b_ih   = (const float*)d_in[6];
    const float* b_hh   = (const float*)d_in[7];
    const float* gc_w   = (const float*)d_in[8];
    const float* gc_b   = (const float*)d_in[9];
    const float* Ws_w   = (const float*)d_in[10];
    const float* Ws_b   = (const float*)d_in[11];
    const float* Wt_w   = (const float*)d_in[12];
    const float* Wt_b   = (const float*)d_in[13];
    const float* v      = (const float*)d_in[14];
    const float* ln_g   = (const float*)d_in[15];
    const float* ln_b   = (const float*)d_in[16];
    const float* comb_b = (const float*)d_in[18];

    float* out = (float*)d_out;              // h_new, then c_lstm
    float* c_out = out + (size_t)BN * HDIM;

    prep_kernel<<<NTB + SCANB + 1, 256>>>(W_ih, W_hh, (const float*)d_in[17], adj,
                                          gc_b, Ws_w, Ws_b, Wt_w, Wt_b);
    prep2_kernel<<<HDIM, 256>>>(gc_w, Ws_w, Wt_w);
    dim3 lstm_grid(NT, 8);                             // 82 x 8 = 656
    lstm_gemm_kernel<<<lstm_grid, 128>>>(x, h, b_ih, b_hh);
    act_kernel<<<BN * HDIM / 256, 256>>>(c, c_out);    // 650
    dim3 spq_grid(NT, 6);                              // 82 x 6 = 492
    spq_gemm_kernel<<<spq_grid, 128>>>();
    gather_kernel<<<BN, 128>>>(gc_b);                  // 1300
    attn_kernel<<<BN, 128>>>(v, ln_g, ln_b);           // 1300
    dim3 comb_grid(NT, 2);                             // 82 x 2 = 164
    comb_gemm_kernel<<<comb_grid, 128>>>(comb_b, out);
}

// round 17
// speedup vs baseline: 1.1201x; 1.1201x over previous
#include <cuda_runtime.h>
#include <math.h>

// Problem constants
#define BATCH   4
#define NNODES  325
#define BN      (BATCH * NNODES)   // 1300
#define IDIM    64
#define HDIM    128
#define G4H     (4 * HDIM)         // 512
#define MAXNB   96
#define LN_EPS  1e-5f
#define GRID    296
#define TPB     256
#define NTH     (GRID * TPB)
#define NTR     41                  // ceil(1300/32) row tiles

// ---------------- scratch (__device__ globals; no allocation) ----------------
__device__ float g_gates[BN * G4H];
__device__ float g_h_lstm[BN * HDIM];
__device__ float g_support[BN * HDIM];
__device__ float g_hgraph[BN * HDIM];
__device__ float g_s[BN * HDIM];
__device__ float g_t[BN * HDIM];
__device__ float g_hatt[BN * HDIM];
__device__ int   g_nbr[BN * MAXNB];
__device__ float g_nbrw[BN * MAXNB];
__device__ int   g_cnt[BN];
// packed weights ([k][col] coalesced layouts)
__device__ float g_Wlstm[192 * G4H];       // rows 0-63 = W_ih^T, 64-191 = W_hh^T
__device__ float g_Wst[HDIM * 256];        // [k][o]: o<128 Ws^T, o>=128 Wt^T
__device__ float g_comb[256 * HDIM];       // [k][o] of comb_w^T
// grid barrier state
__device__ unsigned g_sync_count = 0;
__device__ unsigned g_sync_gen = 0;

__device__ __forceinline__ float sigm_fast(float x) {
    return __fdividef(1.0f, 1.0f + __expf(-x));
}
__device__ __forceinline__ float tanh_fast(float x) {
    float cx = fminf(fmaxf(x, -15.0f), 15.0f);
    float e = __expf(2.0f * cx);
    return __fdividef(e - 1.0f, e + 1.0f);
}

// Software grid barrier: all GRID blocks resident (launch_bounds(256,2), 296<=2*148).
__device__ __forceinline__ void grid_sync() {
    __syncthreads();
    if (threadIdx.x == 0) {
        unsigned gen = *(volatile unsigned*)&g_sync_gen;
        __threadfence();
        unsigned arrived = atomicInc(&g_sync_count, GRID - 1);
        if (arrived == GRID - 1) {
            __threadfence();
            atomicAdd(&g_sync_gen, 1);
        } else {
            while (*(volatile unsigned*)&g_sync_gen == gen) { }
            __threadfence();
        }
    }
    __syncthreads();
}

// ---- 32x64 output tile GEMM, A staged per 64-k chunk, W staged in smem ----
template<int NCH>
__device__ __forceinline__ void tile_gemm(
    const float* const* Ab, const int* Ap, int row0,
    const float* Wg, int wstride, int col0,
    char* smraw, float* acc)
{
    float (*sW)[64] = (float(*)[64])smraw;
    float (*sA)[68] = (float(*)[68])(smraw + 64 * 64 * 4);
    const int tid = threadIdx.x;
    const int oc = (tid & 15) * 4;
    const int m0 = (tid >> 4) * 2;
#pragma unroll
    for (int ch = 0; ch < NCH; ch++) {
        __syncthreads();
        const float* wsrc = Wg + (ch * 64) * wstride + col0;
        for (int idx = tid; idx < 1024; idx += TPB) {
            int kk = idx >> 4, c4 = (idx & 15) * 4;
            *(float4*)&sW[kk][c4] = *(const float4*)&wsrc[kk * wstride + c4];
        }
        const float* ab = Ab[ch];
        const int ap = Ap[ch];
        for (int idx = tid; idx < 512; idx += TPB) {
            int r = idx >> 4, c4 = (idx & 15) * 4;
            int row = row0 + r;
            float4 vv = (row < BN) ? *(const float4*)&ab[row * ap + c4]
                                   : make_float4(0.f, 0.f, 0.f, 0.f);
            *(float4*)&sA[r][c4] = vv;
        }
        __syncthreads();
#pragma unroll 8
        for (int kk = 0; kk < 64; kk++) {
            float4 w = *(const float4*)&sW[kk][oc];
            float a0 = sA[m0][kk], a1 = sA[m0 + 1][kk];
            acc[0] += a0 * w.x; acc[1] += a0 * w.y; acc[2] += a0 * w.z; acc[3] += a0 * w.w;
            acc[4] += a1 * w.x; acc[5] += a1 * w.y; acc[6] += a1 * w.z; acc[7] += a1 * w.w;
        }
    }
}

struct GatSm  { int lst[2][MAXNB]; float wv[2][MAXNB]; };
struct AttnSm { float s[2][HDIM]; float v[HDIM]; int lst[2][MAXNB];
                float sc[2][MAXNB]; float red1[2][4]; float red2[2][4]; };

__global__ void __launch_bounds__(TPB, 2)
mega_kernel(const float* __restrict__ x, const float* __restrict__ adj,
            const float* __restrict__ h, const float* __restrict__ c,
            const float* __restrict__ W_ih, const float* __restrict__ W_hh,
            const float* __restrict__ b_ih, const float* __restrict__ b_hh,
            const float* __restrict__ gc_w, const float* __restrict__ gc_b,
            const float* __restrict__ Ws_w, const float* __restrict__ Ws_b,
            const float* __restrict__ Wt_w, const float* __restrict__ Wt_b,
            const float* __restrict__ v, const float* __restrict__ ln_g,
            const float* __restrict__ ln_b, const float* __restrict__ comb_w,
            const float* __restrict__ comb_b,
            float* __restrict__ out, float* __restrict__ c_out)
{
    __shared__ __align__(16) char smraw[64 * 64 * 4 + 32 * 68 * 4];  // 24.5KB
    const int tid = threadIdx.x;
    const int gtid = blockIdx.x * TPB + tid;

    // ---------------- S0: weight packing + adjacency scan --------------------
    for (int idx = gtid; idx < 192 * G4H; idx += NTH) {
        int k = idx >> 9, g = idx & 511;
        g_Wlstm[idx] = (k < 64) ? __ldg(W_ih + g * IDIM + k)
                                : __ldg(W_hh + g * HDIM + (k - 64));
    }
    for (int idx = gtid; idx < HDIM * 256; idx += NTH) {
        int k = idx >> 8, o = idx & 255;
        g_Wst[idx] = (o < HDIM) ? __ldg(Ws_w + o * HDIM + k)
                                : __ldg(Wt_w + (o - HDIM) * HDIM + k);
    }
    for (int idx = gtid; idx < 256 * HDIM; idx += NTH) {
        int k = idx >> 7, o = idx & 127;
        g_comb[idx] = __ldg(comb_w + o * 2 * HDIM + k);
    }
    {   // adjacency scan: one warp per row, ballot-ordered compaction
        const int lane = tid & 31;
        const int gw = blockIdx.x * (TPB / 32) + (tid >> 5);
        if (gw < BN) {
            const int b = gw / NNODES;
            const int i = gw % NNODES;
            const float* arow = adj + (size_t)b * NNODES * NNODES + (size_t)i * NNODES;
            int cnt = 0;
            const unsigned lt = (1u << lane) - 1u;
            for (int j0 = 0; j0 < NNODES; j0 += 32) {
                int j = j0 + lane;
                float a = (j < NNODES) ? __ldg(arow + j) : 0.0f;
                unsigned m = __ballot_sync(0xffffffffu, a != 0.0f);
                int pos = cnt + __popc(m & lt);
                if (a != 0.0f && pos < MAXNB) {
                    g_nbr[gw * MAXNB + pos]  = j;
                    g_nbrw[gw * MAXNB + pos] = a;
                }
                cnt += __popc(m);
            }
            if (lane == 0) g_cnt[gw] = min(cnt, MAXNB);
        }
    }
    grid_sync();

    // ---------------- S1: LSTM gates GEMM (328 tile tasks) -------------------
    {
        const float* Ab[3] = { x, h, h + 64 };
        const int Ap[3] = { IDIM, HDIM, HDIM };
        for (int task = blockIdx.x; task < NTR * 8; task += GRID) {
            int tr = task % NTR, cg = task / NTR;
            int row0 = tr * 32, col0 = cg * 64;
            float acc[8] = {0.f, 0.f, 0.f, 0.f, 0.f, 0.f, 0.f, 0.f};
            tile_gemm<3>(Ab, Ap, row0, g_Wlstm, G4H, col0, smraw, acc);
            int gcol = col0 + (tid & 15) * 4;
            float4 bi = *(const float4*)&b_ih[gcol];
            float4 bh = *(const float4*)&b_hh[gcol];
            int r0 = row0 + (tid >> 4) * 2;
            if (r0 < BN) {
                float4 o0 = {acc[0] + bi.x + bh.x, acc[1] + bi.y + bh.y,
                             acc[2] + bi.z + bh.z, acc[3] + bi.w + bh.w};
                *(float4*)&g_gates[r0 * G4H + gcol] = o0;
            }
            if (r0 + 1 < BN) {
                float4 o1 = {acc[4] + bi.x + bh.x, acc[5] + bi.y + bh.y,
                             acc[6] + bi.z + bh.z, acc[7] + bi.w + bh.w};
                *(float4*)&g_gates[(r0 + 1) * G4H + gcol] = o1;
            }
        }
    }
    grid_sync();

    // ---------------- S2: LSTM activations (elementwise) ---------------------
    for (int idx = gtid; idx < BN * HDIM; idx += NTH) {
        int node = idx >> 7, u = idx & 127;
        const float* gb = g_gates + node * G4H;
        float ig = sigm_fast(gb[u]);
        float fg = sigm_fast(gb[HDIM + u]);
        float gg = tanh_fast(gb[2 * HDIM + u]);
        float og = sigm_fast(gb[3 * HDIM + u]);
        float cc = fg * c[idx] + ig * gg;
        g_h_lstm[idx] = og * tanh_fast(cc);
        c_out[idx] = cc;
    }
    grid_sync();

    // ---------------- S3: support GEMM (82 tile tasks) -----------------------
    {
        const float* Ab[2] = { g_h_lstm, g_h_lstm + 64 };
        const int Ap[2] = { HDIM, HDIM };
        for (int task = blockIdx.x; task < NTR * 2; task += GRID) {
            int tr = task % NTR, cg = task / NTR;
            int row0 = tr * 32, col0 = cg * 64;
            float acc[8] = {0.f, 0.f, 0.f, 0.f, 0.f, 0.f, 0.f, 0.f};
            tile_gemm<2>(Ab, Ap, row0, gc_w, HDIM, col0, smraw, acc);
            int gcol = col0 + (tid & 15) * 4;
            int r0 = row0 + (tid >> 4) * 2;
            if (r0 < BN) {
                float4 o0 = {acc[0], acc[1], acc[2], acc[3]};
                *(float4*)&g_support[r0 * HDIM + gcol] = o0;
            }
            if (r0 + 1 < BN) {
                float4 o1 = {acc[4], acc[5], acc[6], acc[7]};
                *(float4*)&g_support[(r0 + 1) * HDIM + gcol] = o1;
            }
        }
    }
    grid_sync();

    // ---------------- S4: sparse gather (650 tasks x 2 rows) -----------------
    {
        GatSm* gs = (GatSm*)smraw;
        const int half = tid >> 7, u = tid & 127;
        for (int task = blockIdx.x; task < BN / 2; task += GRID) {
            __syncthreads();
            int row = task * 2 + half;
            int cn = g_cnt[row];
            for (int t = u; t < cn; t += 128) {
                gs->lst[half][t] = g_nbr[row * MAXNB + t];
                gs->wv[half][t]  = g_nbrw[row * MAXNB + t];
            }
            __syncthreads();
            int b = row / NNODES;
            const float* supb = g_support + (size_t)b * NNODES * HDIM;
            float acc = __ldg(gc_b + u);
            int t = 0;
            for (; t + 4 <= cn; t += 4) {
                float h0 = __ldg(supb + (size_t)gs->lst[half][t]     * HDIM + u);
                float h1 = __ldg(supb + (size_t)gs->lst[half][t + 1] * HDIM + u);
                float h2 = __ldg(supb + (size_t)gs->lst[half][t + 2] * HDIM + u);
                float h3 = __ldg(supb + (size_t)gs->lst[half][t + 3] * HDIM + u);
                acc += gs->wv[half][t] * h0 + gs->wv[half][t + 1] * h1
                     + gs->wv[half][t + 2] * h2 + gs->wv[half][t + 3] * h3;
            }
            for (; t < cn; t++)
                acc += gs->wv[half][t] * __ldg(supb + (size_t)gs->lst[half][t] * HDIM + u);
            g_hgraph[row * HDIM + u] = acc;
        }
    }
    grid_sync();

    // ---------------- S5: s/t GEMM (164 tile tasks) --------------------------
    {
        const float* Ab[2] = { g_hgraph, g_hgraph + 64 };
        const int Ap[2] = { HDIM, HDIM };
        for (int task = blockIdx.x; task < NTR * 4; task += GRID) {
            int tr = task % NTR, cg = task / NTR;
            int row0 = tr * 32, col0 = cg * 64;
            float acc[8] = {0.f, 0.f, 0.f, 0.f, 0.f, 0.f, 0.f, 0.f};
            tile_gemm<2>(Ab, Ap, row0, g_Wst, 256, col0, smraw, acc);
            int gcol = col0 + (tid & 15) * 4;                 // 0..255
            float* dst = (gcol < HDIM) ? g_s : g_t;
            int ocol = gcol & 127;
            const float* bp = (gcol < HDIM) ? (Ws_b + ocol) : (Wt_b + ocol);
            float4 bb = *(const float4*)bp;
            int r0 = row0 + (tid >> 4) * 2;
            if (r0 < BN) {
                float4 o0 = {acc[0] + bb.x, acc[1] + bb.y, acc[2] + bb.z, acc[3] + bb.w};
                *(float4*)&dst[r0 * HDIM + ocol] = o0;
            }
            if (r0 + 1 < BN) {
                float4 o1 = {acc[4] + bb.x, acc[5] + bb.y, acc[6] + bb.z, acc[7] + bb.w};
                *(float4*)&dst[(r0 + 1) * HDIM + ocol] = o1;
            }
        }
    }
    grid_sync();

    // ---------------- S6: attention + softmax + context + LN (650 x 2 rows) --
    {
        AttnSm* as = (AttnSm*)smraw;
        const int half = tid >> 7, u = tid & 127;
        const int lane = tid & 31, w4 = (tid >> 5) & 3;
        for (int task = blockIdx.x; task < BN / 2; task += GRID) {
            __syncthreads();
            int row = task * 2 + half;
            as->s[half][u] = g_s[row * HDIM + u];
            if (tid < HDIM) as->v[tid] = __ldg(v + tid);
            int cn = g_cnt[row];
            for (int t = u; t < cn; t += 128) as->lst[half][t] = g_nbr[row * MAXNB + t];
            __syncthreads();
            int b = row / NNODES;
            const float* tb = g_t + (size_t)b * NNODES * HDIM;
            for (int t = w4; t < cn; t += 4) {
                const float* tj = tb + (size_t)as->lst[half][t] * HDIM;
                float p = tanh_fast(as->s[half][lane]      + __ldg(tj + lane))      * as->v[lane]
                        + tanh_fast(as->s[half][lane + 32] + __ldg(tj + lane + 32)) * as->v[lane + 32]
                        + tanh_fast(as->s[half][lane + 64] + __ldg(tj + lane + 64)) * as->v[lane + 64]
                        + tanh_fast(as->s[half][lane + 96] + __ldg(tj + lane + 96)) * as->v[lane + 96];
#pragma unroll
                for (int off = 16; off > 0; off >>= 1)
                    p += __shfl_xor_sync(0xffffffffu, p, off);
                if (lane == 0) as->sc[half][t] = p;
            }
            __syncthreads();
            if (w4 == 0) {   // softmax: warp 0 of each half
                float mx = -1e30f;
                for (int t = lane; t < cn; t += 32) mx = fmaxf(mx, as->sc[half][t]);
#pragma unroll
                for (int off = 16; off > 0; off >>= 1)
                    mx = fmaxf(mx, __shfl_xor_sync(0xffffffffu, mx, off));
                float sm = 0.0f;
                for (int t = lane; t < cn; t += 32) {
                    float e = __expf(as->sc[half][t] - mx);
                    as->sc[half][t] = e;
                    sm += e;
                }
#pragma unroll
                for (int off = 16; off > 0; off >>= 1)
                    sm += __shfl_xor_sync(0xffffffffu, sm, off);
                float inv = __fdividef(1.0f, sm);
                for (int t = lane; t < cn; t += 32) as->sc[half][t] *= inv;
            }
            __syncthreads();
            const float* hgb = g_hgraph + (size_t)b * NNODES * HDIM;
            float acc = 0.0f;
            int t = 0;
            for (; t + 4 <= cn; t += 4) {
                float h0 = __ldg(hgb + (size_t)as->lst[half][t]     * HDIM + u);
                float h1 = __ldg(hgb + (size_t)as->lst[half][t + 1] * HDIM + u);
                float h2 = __ldg(hgb + (size_t)as->lst[half][t + 2] * HDIM + u);
                float h3 = __ldg(hgb + (size_t)as->lst[half][t + 3] * HDIM + u);
                acc += as->sc[half][t] * h0 + as->sc[half][t + 1] * h1
                     + as->sc[half][t + 2] * h2 + as->sc[half][t + 3] * h3;
            }
            for (; t < cn; t++)
                acc += as->sc[half][t] * __ldg(hgb + (size_t)as->lst[half][t] * HDIM + u);

            float s1 = acc, s2 = acc * acc;
#pragma unroll
            for (int off = 16; off > 0; off >>= 1) {
                s1 += __shfl_xor_sync(0xffffffffu, s1, off);
                s2 += __shfl_xor_sync(0xffffffffu, s2, off);
            }
            if (lane == 0) { as->red1[half][w4] = s1; as->red2[half][w4] = s2; }
            __syncthreads();
            float tot1 = as->red1[half][0] + as->red1[half][1] + as->red1[half][2] + as->red1[half][3];
            float tot2 = as->red2[half][0] + as->red2[half][1] + as->red2[half][2] + as->red2[half][3];
            float mu = tot1 * (1.0f / HDIM);
            float var = tot2 * (1.0f / HDIM) - mu * mu;
            g_hatt[row * HDIM + u] =
                __ldg(ln_g + u) * (acc - mu) * rsqrtf(var + LN_EPS) + __ldg(ln_b + u);
        }
    }
    grid_sync();

    // ---------------- S7: combine GEMM (82 tile tasks) -----------------------
    {
        const float* Ab[4] = { g_h_lstm, g_h_lstm + 64, g_hatt, g_hatt + 64 };
        const int Ap[4] = { HDIM, HDIM, HDIM, HDIM };
        for (int task = blockIdx.x; task < NTR * 2; task += GRID) {
            int tr = task % NTR, cg = task / NTR;
            int row0 = tr * 32, col0 = cg * 64;
            float acc[8] = {0.f, 0.f, 0.f, 0.f, 0.f, 0.f, 0.f, 0.f};
            tile_gemm<4>(Ab, Ap, row0, g_comb, HDIM, col0, smraw, acc);
            int gcol = col0 + (tid & 15) * 4;
            float4 cb = *(const float4*)&comb_b[gcol];
            int r0 = row0 + (tid >> 4) * 2;
            if (r0 < BN) {
                float4 o0 = {acc[0] + cb.x, acc[1] + cb.y, acc[2] + cb.z, acc[3] + cb.w};
                *(float4*)&out[r0 * HDIM + gcol] = o0;
            }
            if (r0 + 1 < BN) {
                float4 o1 = {acc[4] + cb.x, acc[5] + cb.y, acc[6] + cb.z, acc[7] + cb.w};
                *(float4*)&out[(r0 + 1) * HDIM + gcol] = o1;
            }
        }
    }
}

// ============================================================================
extern "C" void kernel_launch(void* const* d_in, const int* in_sizes, int n_in,
                              void* d_out, int out_size)
{
    const float* x      = (const float*)d_in[0];
    const float* adj    = (const float*)d_in[1];
    const float* h      = (const float*)d_in[2];
    const float* c      = (const float*)d_in[3];
    const float* W_ih   = (const float*)d_in[4];
    const float* W_hh   = (const float*)d_in[5];
    const float* b_ih   = (const float*)d_in[6];
    const float* b_hh   = (const float*)d_in[7];
    const float* gc_w   = (const float*)d_in[8];
    const float* gc_b   = (const float*)d_in[9];
    const float* Ws_w   = (const float*)d_in[10];
    const float* Ws_b   = (const float*)d_in[11];
    const float* Wt_w   = (const float*)d_in[12];
    const float* Wt_b   = (const float*)d_in[13];
    const float* v      = (const float*)d_in[14];
    const float* ln_g   = (const float*)d_in[15];
    const float* ln_b   = (const float*)d_in[16];
    const float* comb_w = (const float*)d_in[17];
    const float* comb_b = (const float*)d_in[18];

    float* out = (float*)d_out;              // h_new, then c_lstm
    float* c_out = out + (size_t)BN * HDIM;

    mega_kernel<<<GRID, TPB>>>(x, adj, h, c, W_ih, W_hh, b_ih, b_hh,
                               gc_w, gc_b, Ws_w, Ws_b, Wt_w, Wt_b,
                               v, ln_g, ln_b, comb_w, comb_b, out, c_out);
}